// round 1
// baseline (speedup 1.0000x reference)
#include <cuda_runtime.h>
#include <math.h>
#include <math_constants.h>

// Problem constants
#define BB   2
#define LL   2048
#define HH   16
#define DD   64
#define HIDN 1024
#define NBR  4
#define NROWS (BB*LL*HH)   // 65536 (b,l,h) rows
#define NBL   (BB*LL)      // 4096
#define NOUT  128          // 2*D
#define KTAIL 256          // NB*D

// Scratch (allocation-free rule: __device__ globals)
__device__ float g_hid[NBL * NOUT];     // hidden @ W1[0:1024] + b1   (2 MB)
__device__ float g_wstat[12 * NOUT];    // column sums of W1 stat-block rows

// ---------------------------------------------------------------------------
// K0: Wstat[j][o] = sum_{d<64} W1[1024 + j*64 + d][o],  j = p*3+s
// ---------------------------------------------------------------------------
__global__ void wstat_kernel(const float* __restrict__ W1) {
    int j = blockIdx.x;        // 0..11
    int o = threadIdx.x;       // 0..127
    const float* base = W1 + (size_t)(HIDN + j * 64) * NOUT + o;
    float s = 0.f;
#pragma unroll
    for (int d = 0; d < 64; ++d) s += base[(size_t)d * NOUT];
    g_wstat[j * NOUT + o] = s;
}

// ---------------------------------------------------------------------------
// K1: g_hid[4096][128] = hidden[4096][1024] @ W1[0:1024][128] + b1
// Block tile 32 rows x 128 cols, 256 threads, 4x4 per thread, K-tiles of 32.
// ---------------------------------------------------------------------------
__global__ __launch_bounds__(256)
void hid_gemm_kernel(const float* __restrict__ hidden,
                     const float* __restrict__ W1,
                     const float* __restrict__ b1) {
    __shared__ float As[32 * 36];    // [kk][row], row-stride 36
    __shared__ float Bs[32 * 132];   // [kk][col], col-stride 132

    const int tid = threadIdx.x;
    const int m0  = blockIdx.x * 32;
    const int tx  = tid & 31;        // col group: cols tx*4..+3
    const int ty  = tid >> 5;        // row group: rows ty*4..+3 (warp id)
    const int tx4 = tx * 4, ty4 = ty * 4;

    float acc[4][4] = {};

    for (int k0 = 0; k0 < HIDN; k0 += 32) {
        // Load A tile transposed: As[kk][r] = hidden[(m0+r)*1024 + k0+kk]
        {
            int idx = tid;
#pragma unroll
            for (int i = 0; i < 4; ++i, idx += 256) {
                int r = idx >> 5, kk = idx & 31;
                As[kk * 36 + r] = hidden[(size_t)(m0 + r) * HIDN + k0 + kk];
            }
        }
        // Load B tile: Bs[kk][o] = W1[(k0+kk)*128 + o]
        {
            int idx = tid;
#pragma unroll
            for (int i = 0; i < 16; ++i, idx += 256) {
                int kk = idx >> 7, o = idx & 127;
                Bs[kk * 132 + o] = W1[(size_t)(k0 + kk) * NOUT + o];
            }
        }
        __syncthreads();

#pragma unroll 16
        for (int kk = 0; kk < 32; ++kk) {
            const float4 a4 = *reinterpret_cast<const float4*>(&As[kk * 36 + ty4]);
            const float4 b4 = *reinterpret_cast<const float4*>(&Bs[kk * 132 + tx4]);
            float ar[4] = {a4.x, a4.y, a4.z, a4.w};
            float br[4] = {b4.x, b4.y, b4.z, b4.w};
#pragma unroll
            for (int i = 0; i < 4; ++i)
#pragma unroll
                for (int jj = 0; jj < 4; ++jj)
                    acc[i][jj] = fmaf(ar[i], br[jj], acc[i][jj]);
        }
        __syncthreads();
    }

    const float4 bb = *reinterpret_cast<const float4*>(&b1[tx4]);
#pragma unroll
    for (int rr = 0; rr < 4; ++rr) {
        float4 v;
        v.x = acc[rr][0] + bb.x;
        v.y = acc[rr][1] + bb.y;
        v.z = acc[rr][2] + bb.z;
        v.w = acc[rr][3] + bb.w;
        *reinterpret_cast<float4*>(&g_hid[(size_t)(m0 + ty4 + rr) * NOUT + tx4]) = v;
    }
}

// ---------------------------------------------------------------------------
// K2: fused per-head pipeline. One block = 32 consecutive (b,l,h) rows.
//   acc = branches @ W1tail  (K=256 in 4 tiles of 64 == one branch per tile,
//                             stats computed from the staged tile)
//   acc += g_hid + stats @ Wstat ; h = gelu(acc) ; logits = h @ W2 + b2
//   softmax(logits/t), floor, renorm -> out
// Dynamic smem layout (floats):
//   [0,8192)        Bs[64][128]   (reused as Hs[32][132] in epilogue)
//   [8192,10496)    AsT[64][36]
//   [10496,12032)   sWst[12][128]
//   [12032,12544)   sW2[128][4]
//   [12544,12552)   sB2[4] (+pad)
//   [12552,12936)   sStat[32][12]
//   [12936,13064)   sLog[32][4]
// ---------------------------------------------------------------------------
#define K2_SMEM_FLOATS 13064
#define K2_SMEM_BYTES  (K2_SMEM_FLOATS * 4)

__global__ __launch_bounds__(256)
void main_kernel(const float* __restrict__ br0, const float* __restrict__ br1,
                 const float* __restrict__ br2, const float* __restrict__ br3,
                 const float* __restrict__ W1,  const float* __restrict__ W2,
                 const float* __restrict__ b2,  const float* __restrict__ eps_floor,
                 const float* __restrict__ temp, float* __restrict__ out) {
    extern __shared__ float smem[];
    float* Bs    = smem;            // 64*128
    float* AsT   = smem + 8192;     // 64*36
    float* sWst  = smem + 10496;    // 12*128
    float* sW2   = smem + 12032;    // 128*4
    float* sB2   = smem + 12544;    // 4
    float* sStat = smem + 12552;    // 32*12
    float* sLog  = smem + 12936;    // 32*4
    float* Hs    = smem;            // overlays Bs: 32*132

    const int tid = threadIdx.x;
    const int m0  = blockIdx.x * 32;
    const int tx  = tid & 31;
    const int ty  = tid >> 5;       // warp id
    const int tx4 = tx * 4, ty4 = ty * 4;
    const int lane = tid & 31;

    // One-time block loads (covered by first tile's barrier)
    for (int i = tid; i < 12 * NOUT; i += 256) sWst[i] = g_wstat[i];
    for (int i = tid; i < 512; i += 256)       sW2[i]  = W2[i];
    if (tid < 4)                               sB2[tid] = b2[tid];

    float acc[4][4] = {};

    const float* brs[4] = {br0, br1, br2, br3};

#pragma unroll 1
    for (int p = 0; p < NBR; ++p) {
        const float* __restrict__ brp = brs[p];
        // AsT[kk][r] = branch_p[(m0+r)*64 + kk]
        {
            int idx = tid;
#pragma unroll
            for (int i = 0; i < 8; ++i, idx += 256) {
                int kk = idx & 63, r = idx >> 6;
                AsT[kk * 36 + r] = brp[(size_t)(m0 + r) * DD + kk];
            }
        }
        // Bs[kk][o] = W1[(1792 + p*64 + kk)*128 + o]
        {
            int idx = tid;
#pragma unroll
            for (int i = 0; i < 32; ++i, idx += 256) {
                int kk = idx >> 7, o = idx & 127;
                Bs[kk * 128 + o] = W1[(size_t)(HIDN + 768 + p * 64 + kk) * NOUT + o];
            }
        }
        __syncthreads();

        // Stats for branch p: each warp owns 4 rows; 8 lanes per row, 8 vals each
        {
            const int srow = ty * 4 + (lane >> 3);
            const int sub  = lane & 7;
            float s = 0.f, ss = 0.f, mx = -CUDART_INF_F;
#pragma unroll
            for (int j = 0; j < 8; ++j) {
                float v = AsT[(sub * 8 + j) * 36 + srow];
                s += v; ss = fmaf(v, v, ss); mx = fmaxf(mx, v);
            }
#pragma unroll
            for (int d = 1; d < 8; d <<= 1) {
                s  += __shfl_xor_sync(0xffffffffu, s, d);
                ss += __shfl_xor_sync(0xffffffffu, ss, d);
                mx  = fmaxf(mx, __shfl_xor_sync(0xffffffffu, mx, d));
            }
            if (sub == 0) {
                sStat[srow * 12 + p * 3 + 0] = s * (1.f / 64.f);
                sStat[srow * 12 + p * 3 + 1] = sqrtf(fmaxf(ss * (1.f / 64.f), 1e-8f));
                sStat[srow * 12 + p * 3 + 2] = mx;
            }
        }

        // Main FMA loop: 64 x (broadcast a4, per-thread b4, 16 FMA)
#pragma unroll 16
        for (int kk = 0; kk < 64; ++kk) {
            const float4 a4 = *reinterpret_cast<const float4*>(&AsT[kk * 36 + ty4]);
            const float4 b4 = *reinterpret_cast<const float4*>(&Bs[kk * 128 + tx4]);
            float ar[4] = {a4.x, a4.y, a4.z, a4.w};
            float brr[4] = {b4.x, b4.y, b4.z, b4.w};
#pragma unroll
            for (int i = 0; i < 4; ++i)
#pragma unroll
                for (int jj = 0; jj < 4; ++jj)
                    acc[i][jj] = fmaf(ar[i], brr[jj], acc[i][jj]);
        }
        __syncthreads();
    }

    // Epilogue: + hidden part + stats part, gelu, stage h into Hs
#pragma unroll
    for (int rr = 0; rr < 4; ++rr) {
        const int r = ty4 + rr;
        const int m = m0 + r;
        const float4 h4 =
            *reinterpret_cast<const float4*>(&g_hid[(size_t)(m >> 4) * NOUT + tx4]);
        float a0 = acc[rr][0] + h4.x;
        float a1 = acc[rr][1] + h4.y;
        float a2 = acc[rr][2] + h4.z;
        float a3 = acc[rr][3] + h4.w;
#pragma unroll
        for (int j = 0; j < 12; ++j) {
            const float sv = sStat[r * 12 + j];
            const float4 w = *reinterpret_cast<const float4*>(&sWst[j * NOUT + tx4]);
            a0 = fmaf(sv, w.x, a0);
            a1 = fmaf(sv, w.y, a1);
            a2 = fmaf(sv, w.z, a2);
            a3 = fmaf(sv, w.w, a3);
        }
        // exact gelu: x * Phi(x)
        a0 *= normcdff(a0);
        a1 *= normcdff(a1);
        a2 *= normcdff(a2);
        a3 *= normcdff(a3);
        float4 hv = {a0, a1, a2, a3};
        *reinterpret_cast<float4*>(&Hs[r * 132 + tx4]) = hv;
    }
    __syncthreads();

    // logits[32][4] = Hs @ W2 + b2
    if (tid < 128) {
        const int r = tid >> 2, n = tid & 3;
        float s = sB2[n];
#pragma unroll 8
        for (int c = 0; c < 128; ++c)
            s = fmaf(Hs[r * 132 + c], sW2[c * 4 + n], s);
        sLog[r * 4 + n] = s;
    }
    __syncthreads();

    // softmax / floor / renorm, write out
    if (tid < 32) {
        const int m = m0 + tid;
        const int head = m & (HH - 1);
        const float t = fminf(fmaxf(temp[head], 0.2f), 10.f);
        const float inv_t = 1.f / t;
        float l0 = sLog[tid * 4 + 0], l1 = sLog[tid * 4 + 1];
        float l2 = sLog[tid * 4 + 2], l3 = sLog[tid * 4 + 3];
        float mx = fmaxf(fmaxf(l0, l1), fmaxf(l2, l3));
        float e0 = expf((l0 - mx) * inv_t);
        float e1 = expf((l1 - mx) * inv_t);
        float e2 = expf((l2 - mx) * inv_t);
        float e3 = expf((l3 - mx) * inv_t);
        float inv = 1.f / (e0 + e1 + e2 + e3);
        float w0 = e0 * inv, w1 = e1 * inv, w2 = e2 * inv, w3 = e3 * inv;
        const float* ef = &eps_floor[head * 4];
        w0 = fmaxf(w0, fminf(fmaxf(ef[0], 1e-7f), 0.1f));
        w1 = fmaxf(w1, fminf(fmaxf(ef[1], 1e-7f), 0.1f));
        w2 = fmaxf(w2, fminf(fmaxf(ef[2], 1e-7f), 0.1f));
        w3 = fmaxf(w3, fminf(fmaxf(ef[3], 1e-7f), 0.1f));
        float inv2 = 1.f / (w0 + w1 + w2 + w3);
        float4 o = {w0 * inv2, w1 * inv2, w2 * inv2, w3 * inv2};
        *reinterpret_cast<float4*>(&out[(size_t)m * 4]) = o;
    }
}

// ---------------------------------------------------------------------------
// Launch
// ---------------------------------------------------------------------------
extern "C" void kernel_launch(void* const* d_in, const int* in_sizes, int n_in,
                              void* d_out, int out_size) {
    const float* hidden = (const float*)d_in[0];
    const float* br0    = (const float*)d_in[1];
    const float* br1    = (const float*)d_in[2];
    const float* br2    = (const float*)d_in[3];
    const float* br3    = (const float*)d_in[4];
    const float* W1     = (const float*)d_in[5];
    const float* b1     = (const float*)d_in[6];
    const float* W2     = (const float*)d_in[7];
    const float* b2     = (const float*)d_in[8];
    const float* epsf   = (const float*)d_in[9];
    const float* temp   = (const float*)d_in[10];
    float* out = (float*)d_out;

    cudaFuncSetAttribute(main_kernel, cudaFuncAttributeMaxDynamicSharedMemorySize,
                         K2_SMEM_BYTES);

    wstat_kernel<<<12, 128>>>(W1);
    hid_gemm_kernel<<<NBL / 32, 256>>>(hidden, W1, b1);
    main_kernel<<<NROWS / 32, 256, K2_SMEM_BYTES>>>(br0, br1, br2, br3, W1, W2,
                                                    b2, epsf, temp, out);
}

// round 3
// speedup vs baseline: 1.1924x; 1.1924x over previous
#include <cuda_runtime.h>
#include <math.h>
#include <math_constants.h>

typedef unsigned long long ull;

// Problem constants
#define BB   2
#define LL   2048
#define HH   16
#define DD   64
#define HIDN 1024
#define NROWS 65536         // B*L*H
#define NBL   4096          // B*L
#define NOUT  128           // 2*D

// Scratch (__device__ globals: allocation-free rule)
__device__ float g_hidp[4][NBL * NOUT];   // 4 K-split partials of hidden@W1[0:1024] (+b1 in part 0)
__device__ float g_wstat[12 * NOUT];      // column sums of W1 stat-block rows

// ---------------------------------------------------------------------------
// packed f32x2 helpers (FFMA2)
// ---------------------------------------------------------------------------
__device__ __forceinline__ ull fma2(ull a, ull b, ull c) {
    ull d;
    asm("fma.rn.f32x2 %0, %1, %2, %3;" : "=l"(d) : "l"(a), "l"(b), "l"(c));
    return d;
}
__device__ __forceinline__ ull dup2(float x) {
    ull d;
    asm("mov.b64 %0, {%1, %1};" : "=l"(d) : "f"(x));
    return d;
}

// ---------------------------------------------------------------------------
// K1: hidden partial GEMM + wstat.
// Blocks 0..255: rowgroup rg=bid>>2 (64 (b,l)-rows), K-split ks=bid&3 (K=256).
//   g_hidp[ks][row][col] = hidden[rows][Kchunk] @ W1[Kchunk][128] (+b1 if ks==0)
// Blocks 256..267: wstat j = bid-256.
// Thread tile: 4 rows x 8 cols (4 f32x2 col-pairs at {tx4, 64+tx4}).
// Dyn smem: Bs[64][128]=8192f @0, AsT[64][68]=4352f @8192 -> 12544f = 50176B
// ---------------------------------------------------------------------------
#define HID_SMEM_BYTES (12544 * 4)

__global__ __launch_bounds__(256)
void hid_kernel(const float* __restrict__ hidden,
                const float* __restrict__ W1,
                const float* __restrict__ b1) {
    if (blockIdx.x >= 256) {
        // wstat: g_wstat[j][o] = sum_{d<64} W1[1024 + j*64 + d][o]
        const int j = blockIdx.x - 256;
        const int o = threadIdx.x;
        if (o < NOUT) {
            const float* base = W1 + (size_t)(HIDN + j * 64) * NOUT + o;
            float s = 0.f;
#pragma unroll
            for (int d = 0; d < 64; ++d) s += base[(size_t)d * NOUT];
            g_wstat[j * NOUT + o] = s;
        }
        return;
    }

    extern __shared__ float sm[];
    float* Bs  = sm;           // [64][128]
    float* AsT = sm + 8192;    // [64][68]

    const int tid = threadIdx.x;
    const int rg  = blockIdx.x >> 2;
    const int ks  = blockIdx.x & 3;
    const int m0  = rg * 64;           // (b,l)-row base
    const int k0b = ks * 256;
    const int tx  = tid & 15, ty = tid >> 4;
    const int tx4 = tx * 4,  ty4 = ty * 4;

    ull acc[4][4] = {};

    for (int t = 0; t < 4; ++t) {
        const int k0 = k0b + t * 64;
        {
            int idx = tid;
#pragma unroll
            for (int i = 0; i < 16; ++i, idx += 256) {
                int r = idx >> 6, kk = idx & 63;
                AsT[kk * 68 + r] = hidden[(size_t)(m0 + r) * HIDN + k0 + kk];
            }
        }
        {
            int i4 = tid;
#pragma unroll
            for (int i = 0; i < 8; ++i, i4 += 256) {
                int kk = i4 >> 5, c4 = (i4 & 31) * 4;
                *reinterpret_cast<float4*>(&Bs[kk * 128 + c4]) =
                    *reinterpret_cast<const float4*>(&W1[(size_t)(k0 + kk) * NOUT + c4]);
            }
        }
        __syncthreads();

#pragma unroll 8
        for (int kk = 0; kk < 64; ++kk) {
            const float4 a4 = *reinterpret_cast<const float4*>(&AsT[kk * 68 + ty4]);
            const ulonglong2 bv0 =
                *reinterpret_cast<const ulonglong2*>(&Bs[kk * 128 + tx4]);
            const ulonglong2 bv1 =
                *reinterpret_cast<const ulonglong2*>(&Bs[kk * 128 + 64 + tx4]);
            ull ad[4] = {dup2(a4.x), dup2(a4.y), dup2(a4.z), dup2(a4.w)};
            ull bq[4] = {bv0.x, bv0.y, bv1.x, bv1.y};
#pragma unroll
            for (int i = 0; i < 4; ++i)
#pragma unroll
                for (int jj = 0; jj < 4; ++jj)
                    acc[i][jj] = fma2(ad[i], bq[jj], acc[i][jj]);
        }
        __syncthreads();
    }

    // Store partial (part 0 carries b1)
    float* outp = g_hidp[ks];
    float4 bb0 = {0, 0, 0, 0}, bb1 = {0, 0, 0, 0};
    if (ks == 0) {
        bb0 = *reinterpret_cast<const float4*>(&b1[tx4]);
        bb1 = *reinterpret_cast<const float4*>(&b1[64 + tx4]);
    }
#pragma unroll
    for (int rr = 0; rr < 4; ++rr) {
        const int r = ty4 + rr;
        float2 p0 = *reinterpret_cast<float2*>(&acc[rr][0]);
        float2 p1 = *reinterpret_cast<float2*>(&acc[rr][1]);
        float2 p2 = *reinterpret_cast<float2*>(&acc[rr][2]);
        float2 p3 = *reinterpret_cast<float2*>(&acc[rr][3]);
        float4 v0 = {p0.x + bb0.x, p0.y + bb0.y, p1.x + bb0.z, p1.y + bb0.w};
        float4 v1 = {p2.x + bb1.x, p2.y + bb1.y, p3.x + bb1.z, p3.y + bb1.w};
        *reinterpret_cast<float4*>(&outp[(size_t)(m0 + r) * NOUT + tx4]) = v0;
        *reinterpret_cast<float4*>(&outp[(size_t)(m0 + r) * NOUT + 64 + tx4]) = v1;
    }
}

// ---------------------------------------------------------------------------
// K2: fused main. One block = 64 consecutive (b,l,h) rows (= 4 (b,l) x 16 heads).
//   acc = branches @ W1tail (K=256, 4 tiles of 64 = one branch per tile;
//         per-tile stats from staged data)
//   acc += sum_ks g_hidp[ks] + stats @ g_wstat ; h = gelu(acc)
//   logits = h @ W2 + b2 ; softmax(l/t) ; floor ; renorm -> out
// Thread tile: 4 rows x 8 cols (FFMA2).
// Dyn smem (floats):
//   [0, 8192)       Bs[64][128]        (Hs[64][132]=8448 overlays [0,8448) in epilogue)
//   [8448, 12800)   AsT[64][68]
//   [12800, 14336)  sWst[12][128]
//   [14336, 14848)  sW2[128][4]
//   [14848, 14852)  sB2[4]
//   [14852, 15620)  sStat[64][12]
//   [15620, 15876)  sLog[64][4]
// ---------------------------------------------------------------------------
#define MAIN_SMEM_FLOATS 15876
#define MAIN_SMEM_BYTES  (MAIN_SMEM_FLOATS * 4)

__global__ __launch_bounds__(256)
void main_kernel(const float* __restrict__ br0, const float* __restrict__ br1,
                 const float* __restrict__ br2, const float* __restrict__ br3,
                 const float* __restrict__ W1,  const float* __restrict__ W2,
                 const float* __restrict__ b2,  const float* __restrict__ eps_floor,
                 const float* __restrict__ temp, float* __restrict__ out) {
    extern __shared__ float sm[];
    float* Bs    = sm;            // [64][128]
    float* Hs    = sm;            // [64][132] overlay (epilogue)
    float* AsT   = sm + 8448;     // [64][68]
    float* sWst  = sm + 12800;    // [12][128]
    float* sW2   = sm + 14336;    // [128][4]
    float* sB2   = sm + 14848;    // [4]
    float* sStat = sm + 14852;    // [64][12]
    float* sLog  = sm + 15620;    // [64][4]

    const int tid  = threadIdx.x;
    const int m0   = blockIdx.x * 64;
    const int tx   = tid & 15, ty = tid >> 4;
    const int tx4  = tx * 4,  ty4 = ty * 4;
    const int wid  = tid >> 5, lane = tid & 31;

    // One-time loads (first tile barrier covers them)
    for (int i = tid; i < 12 * NOUT; i += 256) sWst[i] = g_wstat[i];
    for (int i = tid; i < 512; i += 256)       sW2[i]  = W2[i];
    if (tid < 4)                               sB2[tid] = b2[tid];

    ull acc[4][4] = {};
    const float* brs[4] = {br0, br1, br2, br3};

#pragma unroll 1
    for (int p = 0; p < 4; ++p) {
        const float* __restrict__ brp = brs[p];
        {
            int idx = tid;
#pragma unroll
            for (int i = 0; i < 16; ++i, idx += 256) {
                int r = idx >> 6, kk = idx & 63;
                AsT[kk * 68 + r] = brp[(size_t)(m0 + r) * DD + kk];
            }
        }
        {
            int i4 = tid;
#pragma unroll
            for (int i = 0; i < 8; ++i, i4 += 256) {
                int kk = i4 >> 5, c4 = (i4 & 31) * 4;
                *reinterpret_cast<float4*>(&Bs[kk * 128 + c4]) =
                    *reinterpret_cast<const float4*>(
                        &W1[(size_t)(HIDN + 768 + p * 64 + kk) * NOUT + c4]);
            }
        }
        __syncthreads();

        // Stats for branch p: warp owns 8 rows; 4 lanes/row, 16 vals each
        {
            const int srow = wid * 8 + (lane & 7);
            const int sub  = lane >> 3;
            float s = 0.f, ssq = 0.f, mx = -CUDART_INF_F;
#pragma unroll
            for (int j = 0; j < 16; ++j) {
                float v = AsT[(sub * 16 + j) * 68 + srow];
                s += v; ssq = fmaf(v, v, ssq); mx = fmaxf(mx, v);
            }
#pragma unroll
            for (int d = 8; d <= 16; d <<= 1) {
                s   += __shfl_xor_sync(0xffffffffu, s, d);
                ssq += __shfl_xor_sync(0xffffffffu, ssq, d);
                mx   = fmaxf(mx, __shfl_xor_sync(0xffffffffu, mx, d));
            }
            if (sub == 0) {
                sStat[srow * 12 + p * 3 + 0] = s * (1.f / 64.f);
                sStat[srow * 12 + p * 3 + 1] = sqrtf(fmaxf(ssq * (1.f / 64.f), 1e-8f));
                sStat[srow * 12 + p * 3 + 2] = mx;
            }
        }

        // Main FFMA2 loop
#pragma unroll 8
        for (int kk = 0; kk < 64; ++kk) {
            const float4 a4 = *reinterpret_cast<const float4*>(&AsT[kk * 68 + ty4]);
            const ulonglong2 bv0 =
                *reinterpret_cast<const ulonglong2*>(&Bs[kk * 128 + tx4]);
            const ulonglong2 bv1 =
                *reinterpret_cast<const ulonglong2*>(&Bs[kk * 128 + 64 + tx4]);
            ull ad[4] = {dup2(a4.x), dup2(a4.y), dup2(a4.z), dup2(a4.w)};
            ull bq[4] = {bv0.x, bv0.y, bv1.x, bv1.y};
#pragma unroll
            for (int i = 0; i < 4; ++i)
#pragma unroll
                for (int jj = 0; jj < 4; ++jj)
                    acc[i][jj] = fma2(ad[i], bq[jj], acc[i][jj]);
        }
        __syncthreads();
    }

    // Epilogue: + hidden partials + stats, gelu, stage into Hs
#pragma unroll
    for (int rr = 0; rr < 4; ++rr) {
        const int r = ty4 + rr;
        const size_t hbase = (size_t)(blockIdx.x * 4 + (r >> 4)) * NOUT;
        float4 h0 = {0, 0, 0, 0}, h1 = {0, 0, 0, 0};
#pragma unroll
        for (int ksi = 0; ksi < 4; ++ksi) {
            const float4 t0 = *reinterpret_cast<const float4*>(&g_hidp[ksi][hbase + tx4]);
            const float4 t1 = *reinterpret_cast<const float4*>(&g_hidp[ksi][hbase + 64 + tx4]);
            h0.x += t0.x; h0.y += t0.y; h0.z += t0.z; h0.w += t0.w;
            h1.x += t1.x; h1.y += t1.y; h1.z += t1.z; h1.w += t1.w;
        }
        float2 p0 = *reinterpret_cast<float2*>(&acc[rr][0]);
        float2 p1 = *reinterpret_cast<float2*>(&acc[rr][1]);
        float2 p2 = *reinterpret_cast<float2*>(&acc[rr][2]);
        float2 p3 = *reinterpret_cast<float2*>(&acc[rr][3]);
        float a[8] = {p0.x + h0.x, p0.y + h0.y, p1.x + h0.z, p1.y + h0.w,
                      p2.x + h1.x, p2.y + h1.y, p3.x + h1.z, p3.y + h1.w};
#pragma unroll
        for (int j = 0; j < 12; ++j) {
            const float sv = sStat[r * 12 + j];
            const float4 w0 = *reinterpret_cast<const float4*>(&sWst[j * NOUT + tx4]);
            const float4 w1 = *reinterpret_cast<const float4*>(&sWst[j * NOUT + 64 + tx4]);
            a[0] = fmaf(sv, w0.x, a[0]); a[1] = fmaf(sv, w0.y, a[1]);
            a[2] = fmaf(sv, w0.z, a[2]); a[3] = fmaf(sv, w0.w, a[3]);
            a[4] = fmaf(sv, w1.x, a[4]); a[5] = fmaf(sv, w1.y, a[5]);
            a[6] = fmaf(sv, w1.z, a[6]); a[7] = fmaf(sv, w1.w, a[7]);
        }
#pragma unroll
        for (int q = 0; q < 8; ++q) a[q] *= normcdff(a[q]);  // exact gelu
        float4 v0 = {a[0], a[1], a[2], a[3]};
        float4 v1 = {a[4], a[5], a[6], a[7]};
        *reinterpret_cast<float4*>(&Hs[r * 132 + tx4]) = v0;
        *reinterpret_cast<float4*>(&Hs[r * 132 + 64 + tx4]) = v1;
    }
    __syncthreads();

    // logits[64][4] = Hs @ W2 + b2  (one thread per (row, n))
    {
        const int r = tid >> 2, n = tid & 3;
        float s = sB2[n];
#pragma unroll 8
        for (int c = 0; c < 128; ++c)
            s = fmaf(Hs[r * 132 + c], sW2[c * 4 + n], s);
        sLog[r * 4 + n] = s;
    }
    __syncthreads();

    // softmax / floor / renorm
    if (tid < 64) {
        const int m = m0 + tid;
        const int head = m & (HH - 1);
        const float t = fminf(fmaxf(temp[head], 0.2f), 10.f);
        const float inv_t = 1.f / t;
        float l0 = sLog[tid * 4 + 0], l1 = sLog[tid * 4 + 1];
        float l2 = sLog[tid * 4 + 2], l3 = sLog[tid * 4 + 3];
        float mx = fmaxf(fmaxf(l0, l1), fmaxf(l2, l3));
        float e0 = expf((l0 - mx) * inv_t);
        float e1 = expf((l1 - mx) * inv_t);
        float e2 = expf((l2 - mx) * inv_t);
        float e3 = expf((l3 - mx) * inv_t);
        float inv = 1.f / (e0 + e1 + e2 + e3);
        float w0 = e0 * inv, w1 = e1 * inv, w2 = e2 * inv, w3 = e3 * inv;
        const float* ef = &eps_floor[head * 4];
        w0 = fmaxf(w0, fminf(fmaxf(ef[0], 1e-7f), 0.1f));
        w1 = fmaxf(w1, fminf(fmaxf(ef[1], 1e-7f), 0.1f));
        w2 = fmaxf(w2, fminf(fmaxf(ef[2], 1e-7f), 0.1f));
        w3 = fmaxf(w3, fminf(fmaxf(ef[3], 1e-7f), 0.1f));
        float inv2 = 1.f / (w0 + w1 + w2 + w3);
        float4 o = {w0 * inv2, w1 * inv2, w2 * inv2, w3 * inv2};
        *reinterpret_cast<float4*>(&out[(size_t)m * 4]) = o;
    }
}

// ---------------------------------------------------------------------------
// Launch
// ---------------------------------------------------------------------------
extern "C" void kernel_launch(void* const* d_in, const int* in_sizes, int n_in,
                              void* d_out, int out_size) {
    const float* hidden = (const float*)d_in[0];
    const float* br0    = (const float*)d_in[1];
    const float* br1    = (const float*)d_in[2];
    const float* br2    = (const float*)d_in[3];
    const float* br3    = (const float*)d_in[4];
    const float* W1     = (const float*)d_in[5];
    const float* b1     = (const float*)d_in[6];
    const float* W2     = (const float*)d_in[7];
    const float* b2     = (const float*)d_in[8];
    const float* epsf   = (const float*)d_in[9];
    const float* temp   = (const float*)d_in[10];
    float* out = (float*)d_out;

    static int attr_done = 0;
    cudaFuncSetAttribute(hid_kernel, cudaFuncAttributeMaxDynamicSharedMemorySize,
                         HID_SMEM_BYTES);
    cudaFuncSetAttribute(main_kernel, cudaFuncAttributeMaxDynamicSharedMemorySize,
                         MAIN_SMEM_BYTES);
    (void)attr_done;

    hid_kernel<<<268, 256, HID_SMEM_BYTES>>>(hidden, W1, b1);
    main_kernel<<<NROWS / 64, 256, MAIN_SMEM_BYTES>>>(br0, br1, br2, br3, W1, W2,
                                                      b2, epsf, temp, out);
}

// round 6
// speedup vs baseline: 1.7308x; 1.4516x over previous
#include <cuda_runtime.h>
#include <cuda_bf16.h>
#include <mma.h>
#include <math.h>
#include <math_constants.h>
#include <stdint.h>

using namespace nvcuda;

typedef unsigned long long ull;

// Problem constants
#define HH    16
#define DD    64
#define HIDN  1024
#define NROWS 65536         // B*L*H
#define NBL   4096          // B*L
#define NOUT  128           // 2*D

// __device__ scratch (allocation-free rule)
__device__ float g_hidp[4][NBL * NOUT];      // K-split partials of hidden@W1[:1024] (+b1 in part 0)
__device__ float g_wstat[12 * NOUT];         // fp32 column sums of W1 stat-block rows
__device__ __nv_bfloat16 g_Bhi[4][8192];     // W1 tail^T per branch chunk [n*64+k], hi part
__device__ __nv_bfloat16 g_Blo[4][8192];     // lo part

// ---------------------------------------------------------------------------
// helpers
// ---------------------------------------------------------------------------
__device__ __forceinline__ ull fma2(ull a, ull b, ull c) {
    ull d; asm("fma.rn.f32x2 %0, %1, %2, %3;" : "=l"(d) : "l"(a), "l"(b), "l"(c));
    return d;
}
__device__ __forceinline__ ull dup2(float x) {
    ull d; asm("mov.b64 %0, {%1, %1};" : "=l"(d) : "f"(x));
    return d;
}
__device__ __forceinline__ uint32_t cvt_bf16x2(float hi_elem, float lo_elem) {
    // bits [15:0] = bf16(lo_elem), [31:16] = bf16(hi_elem)
    uint32_t r;
    asm("cvt.rn.bf16x2.f32 %0, %1, %2;" : "=r"(r) : "f"(hi_elem), "f"(lo_elem));
    return r;
}

// ---------------------------------------------------------------------------
// prep: block 0..3 -> B tiles (transposed, bf16 hi/lo); block 4 -> wstat fp32
// ---------------------------------------------------------------------------
__global__ void prep_kernel(const float* __restrict__ W1) {
    const int p = blockIdx.x;
    if (p < 4) {
        for (int e = threadIdx.x; e < 8192; e += 256) {
            const int k = e >> 7, n = e & 127;
            const float x = W1[(size_t)(HIDN + 768 + p * 64 + k) * NOUT + n];
            const __nv_bfloat16 hi = __float2bfloat16(x);
            const __nv_bfloat16 lo = __float2bfloat16(x - __bfloat162float(hi));
            g_Bhi[p][n * 64 + k] = hi;
            g_Blo[p][n * 64 + k] = lo;
        }
    } else {
        for (int e = threadIdx.x; e < 12 * NOUT; e += 256) {
            const int j = e >> 7, n = e & 127;
            const float* base = W1 + (size_t)(HIDN + j * 64) * NOUT + n;
            float s = 0.f;
#pragma unroll
            for (int d = 0; d < 64; ++d) s += base[(size_t)d * NOUT];
            g_wstat[j * NOUT + n] = s;
        }
    }
}

// ---------------------------------------------------------------------------
// hid: g_hidp[ks] = hidden @ W1[Kchunk][128] (+b1 in ks=0). FFMA2, unchanged.
// ---------------------------------------------------------------------------
#define HID_SMEM_BYTES (12544 * 4)

__global__ __launch_bounds__(256)
void hid_kernel(const float* __restrict__ hidden,
                const float* __restrict__ W1,
                const float* __restrict__ b1) {
    extern __shared__ float sm[];
    float* Bs  = sm;           // [64][128]
    float* AsT = sm + 8192;    // [64][68]

    const int tid = threadIdx.x;
    const int rg  = blockIdx.x >> 2;
    const int ks  = blockIdx.x & 3;
    const int m0  = rg * 64;
    const int k0b = ks * 256;
    const int tx  = tid & 15, ty = tid >> 4;
    const int tx4 = tx * 4,  ty4 = ty * 4;

    ull acc[4][4] = {};

    for (int t = 0; t < 4; ++t) {
        const int k0 = k0b + t * 64;
        {
            int idx = tid;
#pragma unroll
            for (int i = 0; i < 16; ++i, idx += 256) {
                int r = idx >> 6, kk = idx & 63;
                AsT[kk * 68 + r] = hidden[(size_t)(m0 + r) * HIDN + k0 + kk];
            }
        }
        {
            int i4 = tid;
#pragma unroll
            for (int i = 0; i < 8; ++i, i4 += 256) {
                int kk = i4 >> 5, c4 = (i4 & 31) * 4;
                *reinterpret_cast<float4*>(&Bs[kk * 128 + c4]) =
                    *reinterpret_cast<const float4*>(&W1[(size_t)(k0 + kk) * NOUT + c4]);
            }
        }
        __syncthreads();

#pragma unroll 8
        for (int kk = 0; kk < 64; ++kk) {
            const float4 a4 = *reinterpret_cast<const float4*>(&AsT[kk * 68 + ty4]);
            const ulonglong2 bv0 = *reinterpret_cast<const ulonglong2*>(&Bs[kk * 128 + tx4]);
            const ulonglong2 bv1 = *reinterpret_cast<const ulonglong2*>(&Bs[kk * 128 + 64 + tx4]);
            ull ad[4] = {dup2(a4.x), dup2(a4.y), dup2(a4.z), dup2(a4.w)};
            ull bq[4] = {bv0.x, bv0.y, bv1.x, bv1.y};
#pragma unroll
            for (int i = 0; i < 4; ++i)
#pragma unroll
                for (int jj = 0; jj < 4; ++jj)
                    acc[i][jj] = fma2(ad[i], bq[jj], acc[i][jj]);
        }
        __syncthreads();
    }

    float* outp = g_hidp[ks];
    float4 bb0 = {0, 0, 0, 0}, bb1 = {0, 0, 0, 0};
    if (ks == 0) {
        bb0 = *reinterpret_cast<const float4*>(&b1[tx4]);
        bb1 = *reinterpret_cast<const float4*>(&b1[64 + tx4]);
    }
#pragma unroll
    for (int rr = 0; rr < 4; ++rr) {
        const int r = ty4 + rr;
        float2 p0 = *reinterpret_cast<float2*>(&acc[rr][0]);
        float2 p1 = *reinterpret_cast<float2*>(&acc[rr][1]);
        float2 p2 = *reinterpret_cast<float2*>(&acc[rr][2]);
        float2 p3 = *reinterpret_cast<float2*>(&acc[rr][3]);
        float4 v0 = {p0.x + bb0.x, p0.y + bb0.y, p1.x + bb0.z, p1.y + bb0.w};
        float4 v1 = {p2.x + bb1.x, p2.y + bb1.y, p3.x + bb1.z, p3.y + bb1.w};
        *reinterpret_cast<float4*>(&outp[(size_t)(m0 + r) * NOUT + tx4]) = v0;
        *reinterpret_cast<float4*>(&outp[(size_t)(m0 + r) * NOUT + 64 + tx4]) = v1;
    }
}

// ---------------------------------------------------------------------------
// main: wmma bf16 hi/lo GEMM (HMMA tensor pipe).
// M-tile=128 rows, N=128, K=256 (4 branch chunks of 64), 3 hi/lo combos.
// 8 warps: 4(M) x 2(N); warp tile 32x64 = 2x4 wmma 16x16 accumulators.
// Epilogue: D + hid + stats@wstat, gelu, @W2, softmax/floor/renorm.
//
// smem layout (bytes):
//   AH 0      (128x72 bf16 = 18432)       \
//   AL 18432                              | overlaid by Ds[128][136] f32
//   BH 36864  (128n x 72 bf16)            | (69632 B) in epilogue
//   BL 55296  .. 73728                    /
//   WST 73728 (12x128 f32 = 6144)
//   SST 79872 (128x12 f32 = 6144)
//   W2  86016 (128x4 f32 = 2048)
//   HIDC 88064 (8x128 f32 = 4096)
//   SLOG 92160 (128x8 f32 = 4096)
//   total 96256
// ---------------------------------------------------------------------------
#define OFF_AH   0
#define OFF_AL   18432
#define OFF_BH   36864
#define OFF_BL   55296
#define OFF_WST  73728
#define OFF_SST  79872
#define OFF_W2   86016
#define OFF_HIDC 88064
#define OFF_SLOG 92160
#define MAIN_SMEM_BYTES 96256

#define ALD 72     // A/B smem leading dim (bf16 elements)
#define DLD 136    // D smem leading dim (floats)

__global__ __launch_bounds__(256)
void main_wmma_kernel(const float* __restrict__ br0, const float* __restrict__ br1,
                      const float* __restrict__ br2, const float* __restrict__ br3,
                      const float* __restrict__ W2,  const float* __restrict__ b2,
                      const float* __restrict__ eps_floor,
                      const float* __restrict__ temp, float* __restrict__ out) {
    extern __shared__ char smc[];
    __nv_bfloat16* AH = reinterpret_cast<__nv_bfloat16*>(smc + OFF_AH);
    __nv_bfloat16* AL = reinterpret_cast<__nv_bfloat16*>(smc + OFF_AL);
    __nv_bfloat16* BH = reinterpret_cast<__nv_bfloat16*>(smc + OFF_BH);
    __nv_bfloat16* BL = reinterpret_cast<__nv_bfloat16*>(smc + OFF_BL);
    float* Ds    = reinterpret_cast<float*>(smc);             // epilogue overlay
    float* sWst  = reinterpret_cast<float*>(smc + OFF_WST);
    float* sStat = reinterpret_cast<float*>(smc + OFF_SST);
    float* sW2   = reinterpret_cast<float*>(smc + OFF_W2);
    float* hidc  = reinterpret_cast<float*>(smc + OFF_HIDC);
    float* sLog  = reinterpret_cast<float*>(smc + OFF_SLOG);

    const int tid = threadIdx.x;
    const int wid = tid >> 5;
    const int m0  = blockIdx.x * 128;
    const int wm  = wid & 3;           // warp M index (0..3) -> rows wm*32
    const int wn  = wid >> 2;          // warp N index (0..1) -> cols wn*64

    // Prologue one-time loads (covered by chunk-0 __syncthreads)
    for (int i = tid; i < 1024; i += 256) {
        const size_t g = (size_t)(blockIdx.x * 8) * NOUT + i;
        hidc[i] = g_hidp[0][g] + g_hidp[1][g] + g_hidp[2][g] + g_hidp[3][g];
    }
    for (int i = tid; i < 512; i += 256)       sW2[i]  = W2[i];
    for (int i = tid; i < 12 * NOUT; i += 256) sWst[i] = g_wstat[i];

    wmma::fragment<wmma::accumulator, 16, 16, 16, float> acc[2][4];
#pragma unroll
    for (int i = 0; i < 2; ++i)
#pragma unroll
        for (int j = 0; j < 4; ++j) wmma::fill_fragment(acc[i][j], 0.0f);

    const int arow  = tid >> 1;        // staging row (0..127)
    const int ahalf = tid & 1;
    const int kbase = ahalf * 32;

#pragma unroll 1
    for (int p = 0; p < 4; ++p) {
        // ---- stage A (hi/lo) + stats ----
        {
            const float* brp = (p == 0) ? br0 : (p == 1) ? br1 : (p == 2) ? br2 : br3;
            const float* src = brp + (size_t)(m0 + arow) * DD + kbase;
            float s = 0.f, sq = 0.f, mx = -CUDART_INF_F;
#pragma unroll
            for (int j = 0; j < 8; ++j) {
                const float4 v = *reinterpret_cast<const float4*>(src + j * 4);
                s += (v.x + v.y) + (v.z + v.w);
                sq = fmaf(v.x, v.x, sq); sq = fmaf(v.y, v.y, sq);
                sq = fmaf(v.z, v.z, sq); sq = fmaf(v.w, v.w, sq);
                mx = fmaxf(mx, fmaxf(fmaxf(v.x, v.y), fmaxf(v.z, v.w)));
                const uint32_t h0 = cvt_bf16x2(v.y, v.x);
                const uint32_t h1 = cvt_bf16x2(v.w, v.z);
                const float r0 = v.x - __uint_as_float(h0 << 16);
                const float r1 = v.y - __uint_as_float(h0 & 0xffff0000u);
                const float r2 = v.z - __uint_as_float(h1 << 16);
                const float r3 = v.w - __uint_as_float(h1 & 0xffff0000u);
                const uint32_t l0 = cvt_bf16x2(r1, r0);
                const uint32_t l1 = cvt_bf16x2(r3, r2);
                const int eoff = arow * ALD + kbase + j * 4;   // element offset
                uint2 hv = {h0, h1}, lv = {l0, l1};
                *reinterpret_cast<uint2*>(&AH[eoff]) = hv;
                *reinterpret_cast<uint2*>(&AL[eoff]) = lv;
            }
            s  += __shfl_xor_sync(0xffffffffu, s, 1);
            sq += __shfl_xor_sync(0xffffffffu, sq, 1);
            mx  = fmaxf(mx, __shfl_xor_sync(0xffffffffu, mx, 1));
            if (ahalf == 0) {
                sStat[arow * 12 + p * 3 + 0] = s * (1.f / 64.f);
                sStat[arow * 12 + p * 3 + 1] = sqrtf(fmaxf(sq * (1.f / 64.f), 1e-8f));
                sStat[arow * 12 + p * 3 + 2] = mx;
            }
        }
        // ---- stage B (copy precomputed bf16 with pad) ----
        {
            // thread handles n = tid>>1, ks half = (tid&1)*32: 32 bf16 = 64B
            const int n = tid >> 1;
            const int kb = (tid & 1) * 32;
            const uint4* srcH = reinterpret_cast<const uint4*>(&g_Bhi[p][n * 64 + kb]);
            const uint4* srcL = reinterpret_cast<const uint4*>(&g_Blo[p][n * 64 + kb]);
            uint4* dstH = reinterpret_cast<uint4*>(&BH[n * ALD + kb]);
            uint4* dstL = reinterpret_cast<uint4*>(&BL[n * ALD + kb]);
#pragma unroll
            for (int q = 0; q < 4; ++q) { dstH[q] = srcH[q]; dstL[q] = srcL[q]; }
        }
        __syncthreads();

        // ---- HMMA ----
#pragma unroll
        for (int kk = 0; kk < 4; ++kk) {
            wmma::fragment<wmma::matrix_a, 16, 16, 16, __nv_bfloat16, wmma::row_major> ahi[2], alo[2];
#pragma unroll
            for (int i = 0; i < 2; ++i) {
                const int ro = (wm * 32 + i * 16) * ALD + kk * 16;
                wmma::load_matrix_sync(ahi[i], AH + ro, ALD);
                wmma::load_matrix_sync(alo[i], AL + ro, ALD);
            }
#pragma unroll
            for (int j = 0; j < 4; ++j) {
                wmma::fragment<wmma::matrix_b, 16, 16, 16, __nv_bfloat16, wmma::col_major> bhi, blo;
                const int bo = (wn * 64 + j * 16) * ALD + kk * 16;
                wmma::load_matrix_sync(bhi, BH + bo, ALD);
                wmma::load_matrix_sync(blo, BL + bo, ALD);
#pragma unroll
                for (int i = 0; i < 2; ++i) {
                    wmma::mma_sync(acc[i][j], ahi[i], bhi, acc[i][j]);
                    wmma::mma_sync(acc[i][j], alo[i], bhi, acc[i][j]);
                    wmma::mma_sync(acc[i][j], ahi[i], blo, acc[i][j]);
                }
            }
        }
        __syncthreads();   // done reading A/B before next restage (or Ds overlay)
    }

    // ---- store D to smem overlay ----
#pragma unroll
    for (int i = 0; i < 2; ++i)
#pragma unroll
        for (int j = 0; j < 4; ++j)
            wmma::store_matrix_sync(Ds + (wm * 32 + i * 16) * DLD + wn * 64 + j * 16,
                                    acc[i][j], DLD, wmma::mem_row_major);
    __syncthreads();

    // ---- epilogue: hid + stats, gelu, @W2 partials ----
    {
        const int row  = tid >> 1;
        const int half = tid & 1;
        const int c0   = half * 64;
        const float* hrow = &hidc[(row >> 4) * 128];
        const float* drow = &Ds[row * DLD];
        float st[12];
#pragma unroll
        for (int j = 0; j < 12; ++j) st[j] = sStat[row * 12 + j];
        float lg0 = 0.f, lg1 = 0.f, lg2 = 0.f, lg3 = 0.f;
#pragma unroll 8
        for (int ci = 0; ci < 64; ++ci) {
            const int cc = c0 + ci;
            float a = drow[cc] + hrow[cc];
#pragma unroll
            for (int j = 0; j < 12; ++j) a = fmaf(st[j], sWst[j * NOUT + cc], a);
            a *= normcdff(a);                      // exact gelu
            const float4 w = *reinterpret_cast<const float4*>(&sW2[cc * 4]);
            lg0 = fmaf(a, w.x, lg0);
            lg1 = fmaf(a, w.y, lg1);
            lg2 = fmaf(a, w.z, lg2);
            lg3 = fmaf(a, w.w, lg3);
        }
        sLog[row * 8 + half * 4 + 0] = lg0;
        sLog[row * 8 + half * 4 + 1] = lg1;
        sLog[row * 8 + half * 4 + 2] = lg2;
        sLog[row * 8 + half * 4 + 3] = lg3;
    }
    __syncthreads();

    // ---- softmax / floor / renorm ----
    if (tid < 128) {
        const int m = m0 + tid;
        const int head = m & (HH - 1);
        float l0 = sLog[tid * 8 + 0] + sLog[tid * 8 + 4] + b2[0];
        float l1 = sLog[tid * 8 + 1] + sLog[tid * 8 + 5] + b2[1];
        float l2 = sLog[tid * 8 + 2] + sLog[tid * 8 + 6] + b2[2];
        float l3 = sLog[tid * 8 + 3] + sLog[tid * 8 + 7] + b2[3];
        const float t = fminf(fmaxf(temp[head], 0.2f), 10.f);
        const float inv_t = 1.f / t;
        const float mxl = fmaxf(fmaxf(l0, l1), fmaxf(l2, l3));
        const float e0 = expf((l0 - mxl) * inv_t);
        const float e1 = expf((l1 - mxl) * inv_t);
        const float e2 = expf((l2 - mxl) * inv_t);
        const float e3 = expf((l3 - mxl) * inv_t);
        const float inv = 1.f / (e0 + e1 + e2 + e3);
        float w0 = e0 * inv, w1 = e1 * inv, w2 = e2 * inv, w3 = e3 * inv;
        const float* ef = &eps_floor[head * 4];
        w0 = fmaxf(w0, fminf(fmaxf(ef[0], 1e-7f), 0.1f));
        w1 = fmaxf(w1, fminf(fmaxf(ef[1], 1e-7f), 0.1f));
        w2 = fmaxf(w2, fminf(fmaxf(ef[2], 1e-7f), 0.1f));
        w3 = fmaxf(w3, fminf(fmaxf(ef[3], 1e-7f), 0.1f));
        const float inv2 = 1.f / (w0 + w1 + w2 + w3);
        float4 o = {w0 * inv2, w1 * inv2, w2 * inv2, w3 * inv2};
        *reinterpret_cast<float4*>(&out[(size_t)m * 4]) = o;
    }
}

// ---------------------------------------------------------------------------
// Launch
// ---------------------------------------------------------------------------
extern "C" void kernel_launch(void* const* d_in, const int* in_sizes, int n_in,
                              void* d_out, int out_size) {
    const float* hidden = (const float*)d_in[0];
    const float* br0    = (const float*)d_in[1];
    const float* br1    = (const float*)d_in[2];
    const float* br2    = (const float*)d_in[3];
    const float* br3    = (const float*)d_in[4];
    const float* W1     = (const float*)d_in[5];
    const float* b1     = (const float*)d_in[6];
    const float* W2     = (const float*)d_in[7];
    const float* b2     = (const float*)d_in[8];
    const float* epsf   = (const float*)d_in[9];
    const float* temp   = (const float*)d_in[10];
    float* out = (float*)d_out;

    cudaFuncSetAttribute(hid_kernel, cudaFuncAttributeMaxDynamicSharedMemorySize,
                         HID_SMEM_BYTES);
    cudaFuncSetAttribute(main_wmma_kernel, cudaFuncAttributeMaxDynamicSharedMemorySize,
                         MAIN_SMEM_BYTES);

    prep_kernel<<<5, 256>>>(W1);
    hid_kernel<<<256, 256, HID_SMEM_BYTES>>>(hidden, W1, b1);
    main_wmma_kernel<<<NROWS / 128, 256, MAIN_SMEM_BYTES>>>(br0, br1, br2, br3, W2,
                                                            b2, epsf, temp, out);
}